// round 4
// baseline (speedup 1.0000x reference)
#include <cuda_runtime.h>
#include <math.h>

#define N_MAX 100000

// ---- scratch (static __device__ arrays; allocation-free) ----
__device__ __align__(16) float g_A[N_MAX * 32];
__device__ __align__(16) float g_B[N_MAX * 32];
__device__ __align__(16) float g_sumh[N_MAX * 32];
__device__ __align__(16) float g_cnt[N_MAX];
__device__ __align__(16) float g_sumout[N_MAX * 4];
__device__ __align__(16) float g_stats[8];

// ---- f32x2 / LDS.128 / red.v4 helpers ----
__device__ __forceinline__ unsigned long long pack2(float x, float y) {
    unsigned long long r;
    asm("mov.b64 %0, {%1,%2};" : "=l"(r) : "f"(x), "f"(y));
    return r;
}
__device__ __forceinline__ void unpack2(unsigned long long v, float& x, float& y) {
    asm("mov.b64 {%0,%1}, %2;" : "=f"(x), "=f"(y) : "l"(v));
}
__device__ __forceinline__ void fma2(unsigned long long& d, unsigned long long a, unsigned long long b) {
    asm("fma.rn.f32x2 %0, %1, %2, %3;" : "=l"(d) : "l"(a), "l"(b), "l"(d));
}
__device__ __forceinline__ void lds_pair(unsigned addr, unsigned long long& a, unsigned long long& b) {
    asm volatile("ld.shared.v2.u64 {%0,%1}, [%2];" : "=l"(a), "=l"(b) : "r"(addr));
}
__device__ __forceinline__ void red4(float* p, float a, float b, float c, float d) {
    asm volatile("red.global.add.v4.f32 [%0], {%1,%2,%3,%4};"
                 :: "l"(p), "f"(a), "f"(b), "f"(c), "f"(d) : "memory");
}

// ---- K0: zero accumulators ----
__global__ void k_zero(int n) {
    int i = blockIdx.x * blockDim.x + threadIdx.x;
    int stride = gridDim.x * blockDim.x;
    float4 z = make_float4(0.f, 0.f, 0.f, 0.f);
    float4* a = (float4*)g_sumh;  int na = n * 8;
    for (int t = i; t < na; t += stride) a[t] = z;
    float4* b = (float4*)g_sumout; int nb = n;
    for (int t = i; t < nb; t += stride) b[t] = z;
    float4* c = (float4*)g_cnt;   int nc = n >> 2;
    for (int t = i; t < nc; t += stride) c[t] = z;
    if (i < 8) g_stats[i] = 0.f;
}

// ---- K1: batchnorm statistics (sum, sumsq per channel) ----
__global__ void k_stats(const float4* __restrict__ x, int n) {
    float sx = 0, sy = 0, sz = 0, sw = 0, qx = 0, qy = 0, qz = 0, qw = 0;
    for (int i = blockIdx.x * blockDim.x + threadIdx.x; i < n; i += gridDim.x * blockDim.x) {
        float4 v = x[i];
        sx += v.x; sy += v.y; sz += v.z; sw += v.w;
        qx += v.x * v.x; qy += v.y * v.y; qz += v.z * v.z; qw += v.w * v.w;
    }
    #pragma unroll
    for (int off = 16; off; off >>= 1) {
        sx += __shfl_down_sync(0xffffffffu, sx, off);
        sy += __shfl_down_sync(0xffffffffu, sy, off);
        sz += __shfl_down_sync(0xffffffffu, sz, off);
        sw += __shfl_down_sync(0xffffffffu, sw, off);
        qx += __shfl_down_sync(0xffffffffu, qx, off);
        qy += __shfl_down_sync(0xffffffffu, qy, off);
        qz += __shfl_down_sync(0xffffffffu, qz, off);
        qw += __shfl_down_sync(0xffffffffu, qw, off);
    }
    if ((threadIdx.x & 31) == 0) {
        atomicAdd(&g_stats[0], sx); atomicAdd(&g_stats[1], sy);
        atomicAdd(&g_stats[2], sz); atomicAdd(&g_stats[3], sw);
        atomicAdd(&g_stats[4], qx); atomicAdd(&g_stats[5], qy);
        atomicAdd(&g_stats[6], qz); atomicAdd(&g_stats[7], qw);
    }
}

// ---- K2: per-node BN + encoder layer-1 split (A = xn@(W1a-W1b)+b1, B = xn@W1b) ----
__global__ void k_pre(const float4* __restrict__ x,
                      const float* __restrict__ gamma, const float* __restrict__ beta,
                      const float* __restrict__ eW1, const float* __restrict__ eb1,
                      int n, float invN) {
    __shared__ float sWd[128], sWb[128], sb1[32], sScale[4], sShift[4];
    int t = threadIdx.x;
    if (t < 128) {
        int c = t >> 5, o = t & 31;
        float wa = eW1[c * 32 + o], wb = eW1[(4 + c) * 32 + o];
        sWd[t] = wa - wb; sWb[t] = wb;
    }
    if (t < 32) sb1[t] = eb1[t];
    if (t < 4) {
        float m = g_stats[t] * invN;
        float v = g_stats[4 + t] * invN - m * m;
        float s = rsqrtf(v + 1e-5f) * gamma[t];
        sScale[t] = s; sShift[t] = beta[t] - m * s;
    }
    __syncthreads();
    for (int i = blockIdx.x * blockDim.x + t; i < n; i += gridDim.x * blockDim.x) {
        float4 xv = x[i];
        float xn[4];
        xn[0] = xv.x * sScale[0] + sShift[0];
        xn[1] = xv.y * sScale[1] + sShift[1];
        xn[2] = xv.z * sScale[2] + sShift[2];
        xn[3] = xv.w * sScale[3] + sShift[3];
        float a[32], b[32];
        #pragma unroll
        for (int o = 0; o < 32; o++) {
            float av = sb1[o], bv = 0.f;
            #pragma unroll
            for (int c = 0; c < 4; c++) {
                av += xn[c] * sWd[c * 32 + o];
                bv += xn[c] * sWb[c * 32 + o];
            }
            a[o] = av; b[o] = bv;
        }
        float4* Ao = (float4*)(g_A + (size_t)i * 32);
        float4* Bo = (float4*)(g_B + (size_t)i * 32);
        #pragma unroll
        for (int q = 0; q < 8; q++) {
            Ao[q] = make_float4(a[4*q], a[4*q+1], a[4*q+2], a[4*q+3]);
            Bo[q] = make_float4(b[4*q], b[4*q+1], b[4*q+2], b[4*q+3]);
        }
    }
}

// ---- K3: encoder edge pass: msg = relu(relu(A[tgt]+B[src]) @ eW2 + eb2) -> red into sum_h[tgt] ----
__global__ void __launch_bounds__(256) k_enc(const int* __restrict__ ei,
                                             const float* __restrict__ eW2,
                                             const float* __restrict__ eb2, int E) {
    __shared__ __align__(16) float sW[1024];
    __shared__ __align__(16) float sb[32];
    for (int t = threadIdx.x; t < 1024; t += blockDim.x) sW[t] = eW2[t];
    if (threadIdx.x < 32) sb[threadIdx.x] = eb2[threadIdx.x];
    __syncthreads();
    unsigned swa = (unsigned)__cvta_generic_to_shared(sW);
    unsigned sba = (unsigned)__cvta_generic_to_shared(sb);

    int e = blockIdx.x * blockDim.x + threadIdx.x;
    if (e >= E) return;
    int src = ei[e], tgt = ei[E + e];

    const float4* Ar = (const float4*)(g_A + (size_t)tgt * 32);
    const float4* Br = (const float4*)(g_B + (size_t)src * 32);
    float u[32];
    #pragma unroll
    for (int q = 0; q < 8; q++) {
        float4 a = Ar[q], b = Br[q];
        u[4*q]   = fmaxf(a.x + b.x, 0.f);
        u[4*q+1] = fmaxf(a.y + b.y, 0.f);
        u[4*q+2] = fmaxf(a.z + b.z, 0.f);
        u[4*q+3] = fmaxf(a.w + b.w, 0.f);
    }
    unsigned long long acc[16];
    #pragma unroll
    for (int q = 0; q < 8; q++) lds_pair(sba + q * 16, acc[2*q], acc[2*q+1]);
    #pragma unroll
    for (int k = 0; k < 32; k++) {
        unsigned long long up = pack2(u[k], u[k]);
        #pragma unroll
        for (int q = 0; q < 8; q++) {
            unsigned long long w0, w1;
            lds_pair(swa + (unsigned)(k * 128 + q * 16), w0, w1);
            fma2(acc[2*q], up, w0);
            fma2(acc[2*q+1], up, w1);
        }
    }
    float* dst = g_sumh + (size_t)tgt * 32;
    #pragma unroll
    for (int q = 0; q < 8; q++) {
        float m0, m1, m2, m3;
        unpack2(acc[2*q], m0, m1);
        unpack2(acc[2*q+1], m2, m3);
        red4(dst + 4*q, fmaxf(m0, 0.f), fmaxf(m1, 0.f), fmaxf(m2, 0.f), fmaxf(m3, 0.f));
    }
    atomicAdd(&g_cnt[tgt], 1.0f);
}

// ---- K4: per-node: h=mean, mu/logvar heads, reparam z, decoder layer-1 split into g_A/g_B ----
__global__ void k_mid(const float* __restrict__ mW, const float* __restrict__ mb,
                      const float* __restrict__ vW, const float* __restrict__ vb,
                      const float* __restrict__ dW1, const float* __restrict__ db1,
                      const float* __restrict__ eps2,
                      float* __restrict__ out_mu, float* __restrict__ out_lv, int n) {
    __shared__ float smW[64], svW[64], sWd[64], sWb[64], sdb1[32], smb[2], svb[2];
    int t = threadIdx.x;
    if (t < 64) { smW[t] = mW[t]; svW[t] = vW[t]; }
    if (t < 32) {
        sdb1[t] = db1[t];
        sWd[t]      = dW1[t]      - dW1[64 + t];
        sWd[32 + t] = dW1[32 + t] - dW1[96 + t];
        sWb[t]      = dW1[64 + t];
        sWb[32 + t] = dW1[96 + t];
    }
    if (t < 2) { smb[t] = mb[t]; svb[t] = vb[t]; }
    __syncthreads();
    for (int i = blockIdx.x * blockDim.x + t; i < n; i += gridDim.x * blockDim.x) {
        const float4* hr = (const float4*)(g_sumh + (size_t)i * 32);
        float inv = 1.0f / fmaxf(g_cnt[i], 1.0f);
        float h[32];
        #pragma unroll
        for (int q = 0; q < 8; q++) {
            float4 v = hr[q];
            h[4*q]   = v.x * inv;
            h[4*q+1] = v.y * inv;
            h[4*q+2] = v.z * inv;
            h[4*q+3] = v.w * inv;
        }
        float mu0 = smb[0], mu1 = smb[1], lv0 = svb[0], lv1 = svb[1];
        #pragma unroll
        for (int o = 0; o < 32; o++) {
            mu0 += h[o] * smW[2*o]; mu1 += h[o] * smW[2*o+1];
            lv0 += h[o] * svW[2*o]; lv1 += h[o] * svW[2*o+1];
        }
        float2 ep = ((const float2*)eps2)[i];
        float z0 = mu0 + ep.x * expf(0.5f * lv0);
        float z1 = mu1 + ep.y * expf(0.5f * lv1);
        ((float2*)out_mu)[i] = make_float2(mu0, mu1);
        ((float2*)out_lv)[i] = make_float2(lv0, lv1);
        float a[32], b[32];
        #pragma unroll
        for (int o = 0; o < 32; o++) {
            a[o] = sdb1[o] + z0 * sWd[o] + z1 * sWd[32 + o];
            b[o] = z0 * sWb[o] + z1 * sWb[32 + o];
        }
        float4* Ao = (float4*)(g_A + (size_t)i * 32);
        float4* Bo = (float4*)(g_B + (size_t)i * 32);
        #pragma unroll
        for (int q = 0; q < 8; q++) {
            Ao[q] = make_float4(a[4*q], a[4*q+1], a[4*q+2], a[4*q+3]);
            Bo[q] = make_float4(b[4*q], b[4*q+1], b[4*q+2], b[4*q+3]);
        }
    }
}

// ---- K5: decoder edge pass: v=relu(relu(A[tgt]+B[src])@dW2+db2); o4=v@dW3+db3 -> red sum_out[tgt] ----
__global__ void __launch_bounds__(256) k_dec(const int* __restrict__ ei,
                                             const float* __restrict__ dW2,
                                             const float* __restrict__ db2,
                                             const float* __restrict__ dW3,
                                             const float* __restrict__ db3, int E) {
    __shared__ __align__(16) float sW[1024];
    __shared__ __align__(16) float sW3[128];
    __shared__ __align__(16) float sb[32];
    __shared__ __align__(16) float sb3[4];
    for (int t = threadIdx.x; t < 1024; t += blockDim.x) sW[t] = dW2[t];
    if (threadIdx.x < 128) sW3[threadIdx.x] = dW3[threadIdx.x];
    if (threadIdx.x < 32) sb[threadIdx.x] = db2[threadIdx.x];
    if (threadIdx.x < 4) sb3[threadIdx.x] = db3[threadIdx.x];
    __syncthreads();
    unsigned swa  = (unsigned)__cvta_generic_to_shared(sW);
    unsigned sw3a = (unsigned)__cvta_generic_to_shared(sW3);
    unsigned sba  = (unsigned)__cvta_generic_to_shared(sb);
    unsigned sb3a = (unsigned)__cvta_generic_to_shared(sb3);

    int e = blockIdx.x * blockDim.x + threadIdx.x;
    if (e >= E) return;
    int src = ei[e], tgt = ei[E + e];

    const float4* Ar = (const float4*)(g_A + (size_t)tgt * 32);
    const float4* Br = (const float4*)(g_B + (size_t)src * 32);
    float u[32];
    #pragma unroll
    for (int q = 0; q < 8; q++) {
        float4 a = Ar[q], b = Br[q];
        u[4*q]   = fmaxf(a.x + b.x, 0.f);
        u[4*q+1] = fmaxf(a.y + b.y, 0.f);
        u[4*q+2] = fmaxf(a.z + b.z, 0.f);
        u[4*q+3] = fmaxf(a.w + b.w, 0.f);
    }
    unsigned long long acc[16];
    #pragma unroll
    for (int q = 0; q < 8; q++) lds_pair(sba + q * 16, acc[2*q], acc[2*q+1]);
    #pragma unroll
    for (int k = 0; k < 32; k++) {
        unsigned long long up = pack2(u[k], u[k]);
        #pragma unroll
        for (int q = 0; q < 8; q++) {
            unsigned long long w0, w1;
            lds_pair(swa + (unsigned)(k * 128 + q * 16), w0, w1);
            fma2(acc[2*q], up, w0);
            fma2(acc[2*q+1], up, w1);
        }
    }
    float v[32];
    #pragma unroll
    for (int q = 0; q < 8; q++) {
        float m0, m1, m2, m3;
        unpack2(acc[2*q], m0, m1);
        unpack2(acc[2*q+1], m2, m3);
        v[4*q]   = fmaxf(m0, 0.f);
        v[4*q+1] = fmaxf(m1, 0.f);
        v[4*q+2] = fmaxf(m2, 0.f);
        v[4*q+3] = fmaxf(m3, 0.f);
    }
    unsigned long long oc0, oc1;
    lds_pair(sb3a, oc0, oc1);
    #pragma unroll
    for (int o = 0; o < 32; o++) {
        unsigned long long vp = pack2(v[o], v[o]);
        unsigned long long w0, w1;
        lds_pair(sw3a + (unsigned)(o * 16), w0, w1);
        fma2(oc0, vp, w0);
        fma2(oc1, vp, w1);
    }
    float r0, r1, r2, r3;
    unpack2(oc0, r0, r1);
    unpack2(oc1, r2, r3);
    red4(g_sumout + (size_t)tgt * 4, r0, r1, r2, r3);
}

// ---- K6: per-node output mean ----
__global__ void k_out(float* __restrict__ out, int n) {
    for (int i = blockIdx.x * blockDim.x + threadIdx.x; i < n; i += gridDim.x * blockDim.x) {
        float inv = 1.0f / fmaxf(g_cnt[i], 1.0f);
        float4 s = ((const float4*)g_sumout)[i];
        ((float4*)out)[i] = make_float4(s.x * inv, s.y * inv, s.z * inv, s.w * inv);
    }
}

extern "C" void kernel_launch(void* const* d_in, const int* in_sizes, int n_in,
                              void* d_out, int out_size) {
    const float* x     = (const float*)d_in[0];
    const int*   ei    = (const int*)d_in[1];
    const float* eps   = (const float*)d_in[2];
    const float* gamma = (const float*)d_in[3];
    const float* beta  = (const float*)d_in[4];
    const float* eW1   = (const float*)d_in[5];
    const float* eb1   = (const float*)d_in[6];
    const float* eW2   = (const float*)d_in[7];
    const float* eb2   = (const float*)d_in[8];
    const float* mW    = (const float*)d_in[9];
    const float* mb    = (const float*)d_in[10];
    const float* vW    = (const float*)d_in[11];
    const float* vb    = (const float*)d_in[12];
    const float* dW1   = (const float*)d_in[13];
    const float* db1   = (const float*)d_in[14];
    const float* dW2   = (const float*)d_in[15];
    const float* db2   = (const float*)d_in[16];
    const float* dW3   = (const float*)d_in[17];
    const float* db3   = (const float*)d_in[18];

    int n = in_sizes[0] / 4;
    int E = in_sizes[1] / 2;

    float* out    = (float*)d_out;
    float* out_mu = out + (size_t)n * 4;
    float* out_lv = out + (size_t)n * 6;

    int nb = (n + 255) / 256;
    int eb = (E + 255) / 256;

    k_zero<<<512, 256>>>(n);
    k_stats<<<256, 256>>>((const float4*)x, n);
    k_pre<<<nb, 256>>>((const float4*)x, gamma, beta, eW1, eb1, n, 1.0f / (float)n);
    k_enc<<<eb, 256>>>(ei, eW2, eb2, E);
    k_mid<<<nb, 256>>>(mW, mb, vW, vb, dW1, db1, eps, out_mu, out_lv, n);
    k_dec<<<eb, 256>>>(ei, dW2, db2, dW3, db3, E);
    k_out<<<nb, 256>>>(out, n);
}

// round 5
// speedup vs baseline: 1.1333x; 1.1333x over previous
#include <cuda_runtime.h>
#include <math.h>

#define N_MAX 100000
typedef unsigned long long ull;

// ---- scratch (static __device__ arrays; allocation-free) ----
__device__ __align__(16) float g_A[N_MAX * 32];
__device__ __align__(16) float g_B[N_MAX * 32];
__device__ __align__(16) float g_sumh[N_MAX * 32];
__device__ __align__(16) float g_cnt[N_MAX];
__device__ __align__(16) float g_sumout[N_MAX * 4];
__device__ __align__(16) float g_stats[8];

// ---- f32x2 / LDS.128 / red helpers ----
__device__ __forceinline__ ull pack2(float x, float y) {
    ull r; asm("mov.b64 %0, {%1,%2};" : "=l"(r) : "f"(x), "f"(y)); return r;
}
__device__ __forceinline__ void unpack2(ull v, float& x, float& y) {
    asm("mov.b64 {%0,%1}, %2;" : "=f"(x), "=f"(y) : "l"(v));
}
__device__ __forceinline__ void fma2(ull& d, ull a, ull b) {
    asm("fma.rn.f32x2 %0, %1, %2, %3;" : "=l"(d) : "l"(a), "l"(b), "l"(d));
}
__device__ __forceinline__ ull addp(ull a, ull b) {
    ull r; asm("add.rn.f32x2 %0, %1, %2;" : "=l"(r) : "l"(a), "l"(b)); return r;
}
__device__ __forceinline__ void lds_pair(unsigned addr, ull& a, ull& b) {
    asm volatile("ld.shared.v2.u64 {%0,%1}, [%2];" : "=l"(a), "=l"(b) : "r"(addr));
}
__device__ __forceinline__ void red4(float* p, float a, float b, float c, float d) {
    asm volatile("red.global.add.v4.f32 [%0], {%1,%2,%3,%4};"
                 :: "l"(p), "f"(a), "f"(b), "f"(c), "f"(d) : "memory");
}
__device__ __forceinline__ void redf(float* p, float v) {
    asm volatile("red.global.add.f32 [%0], %1;" :: "l"(p), "f"(v) : "memory");
}
__device__ __forceinline__ ull shflx(ull v, int m) {
    return __shfl_xor_sync(0xffffffffu, v, m);
}

// quad reduce-scatter: acc[16] (32 outputs, k-partial) -> t4[4] (lane owns outputs [qlane*8, qlane*8+8))
__device__ __forceinline__ void quad_rs(const ull acc[16], int qlane, ull t4[4]) {
    ull t8[8];
    bool hi2 = (qlane & 2) != 0;
    #pragma unroll
    for (int i = 0; i < 8; i++) {
        ull sel  = hi2 ? acc[i]     : acc[i + 8];
        ull keep = hi2 ? acc[i + 8] : acc[i];
        t8[i] = addp(keep, shflx(sel, 2));
    }
    bool hi1 = (qlane & 1) != 0;
    #pragma unroll
    for (int i = 0; i < 4; i++) {
        ull sel  = hi1 ? t8[i]     : t8[i + 4];
        ull keep = hi1 ? t8[i + 4] : t8[i];
        t4[i] = addp(keep, shflx(sel, 1));
    }
}

// ---- K0: zero accumulators ----
__global__ void k_zero(int n) {
    int i = blockIdx.x * blockDim.x + threadIdx.x;
    int stride = gridDim.x * blockDim.x;
    float4 z = make_float4(0.f, 0.f, 0.f, 0.f);
    float4* a = (float4*)g_sumh;   int na = n * 8;
    for (int t = i; t < na; t += stride) a[t] = z;
    float4* b = (float4*)g_sumout; int nb = n;
    for (int t = i; t < nb; t += stride) b[t] = z;
    float4* c = (float4*)g_cnt;    int nc = n >> 2;
    for (int t = i; t < nc; t += stride) c[t] = z;
    if (i < 8) g_stats[i] = 0.f;
}

// ---- K1: batchnorm statistics ----
__global__ void k_stats(const float4* __restrict__ x, int n) {
    float sx = 0, sy = 0, sz = 0, sw = 0, qx = 0, qy = 0, qz = 0, qw = 0;
    for (int i = blockIdx.x * blockDim.x + threadIdx.x; i < n; i += gridDim.x * blockDim.x) {
        float4 v = x[i];
        sx += v.x; sy += v.y; sz += v.z; sw += v.w;
        qx += v.x * v.x; qy += v.y * v.y; qz += v.z * v.z; qw += v.w * v.w;
    }
    #pragma unroll
    for (int off = 16; off; off >>= 1) {
        sx += __shfl_down_sync(0xffffffffu, sx, off);
        sy += __shfl_down_sync(0xffffffffu, sy, off);
        sz += __shfl_down_sync(0xffffffffu, sz, off);
        sw += __shfl_down_sync(0xffffffffu, sw, off);
        qx += __shfl_down_sync(0xffffffffu, qx, off);
        qy += __shfl_down_sync(0xffffffffu, qy, off);
        qz += __shfl_down_sync(0xffffffffu, qz, off);
        qw += __shfl_down_sync(0xffffffffu, qw, off);
    }
    if ((threadIdx.x & 31) == 0) {
        atomicAdd(&g_stats[0], sx); atomicAdd(&g_stats[1], sy);
        atomicAdd(&g_stats[2], sz); atomicAdd(&g_stats[3], sw);
        atomicAdd(&g_stats[4], qx); atomicAdd(&g_stats[5], qy);
        atomicAdd(&g_stats[6], qz); atomicAdd(&g_stats[7], qw);
    }
}

// ---- K2: BN + encoder layer-1 split ----
__global__ void k_pre(const float4* __restrict__ x,
                      const float* __restrict__ gamma, const float* __restrict__ beta,
                      const float* __restrict__ eW1, const float* __restrict__ eb1,
                      int n, float invN) {
    __shared__ float sWd[128], sWb[128], sb1[32], sScale[4], sShift[4];
    int t = threadIdx.x;
    if (t < 128) {
        int c = t >> 5, o = t & 31;
        float wa = eW1[c * 32 + o], wb = eW1[(4 + c) * 32 + o];
        sWd[t] = wa - wb; sWb[t] = wb;
    }
    if (t < 32) sb1[t] = eb1[t];
    if (t < 4) {
        float m = g_stats[t] * invN;
        float v = g_stats[4 + t] * invN - m * m;
        float s = rsqrtf(v + 1e-5f) * gamma[t];
        sScale[t] = s; sShift[t] = beta[t] - m * s;
    }
    __syncthreads();
    for (int i = blockIdx.x * blockDim.x + t; i < n; i += gridDim.x * blockDim.x) {
        float4 xv = x[i];
        float xn[4];
        xn[0] = xv.x * sScale[0] + sShift[0];
        xn[1] = xv.y * sScale[1] + sShift[1];
        xn[2] = xv.z * sScale[2] + sShift[2];
        xn[3] = xv.w * sScale[3] + sShift[3];
        float a[32], b[32];
        #pragma unroll
        for (int o = 0; o < 32; o++) {
            float av = sb1[o], bv = 0.f;
            #pragma unroll
            for (int c = 0; c < 4; c++) {
                av += xn[c] * sWd[c * 32 + o];
                bv += xn[c] * sWb[c * 32 + o];
            }
            a[o] = av; b[o] = bv;
        }
        float4* Ao = (float4*)(g_A + (size_t)i * 32);
        float4* Bo = (float4*)(g_B + (size_t)i * 32);
        #pragma unroll
        for (int q = 0; q < 8; q++) {
            Ao[q] = make_float4(a[4*q], a[4*q+1], a[4*q+2], a[4*q+3]);
            Bo[q] = make_float4(b[4*q], b[4*q+1], b[4*q+2], b[4*q+3]);
        }
    }
}

// ===================== quad-cooperative encoder edge pass =====================
// warp = 8 quads; each quad handles 2 edges; lane owns k in {4q+j, 16+4q+j}
__global__ void __launch_bounds__(256) k_enc(const int* __restrict__ ei,
                                             const float* __restrict__ eW2,
                                             const float* __restrict__ eb2, int E) {
    __shared__ __align__(16) float sW[1024];
    __shared__ __align__(16) float sb[32];
    // swizzled store: chunk c of row k lands at phys chunk ((c + (k>>2)) & 7)
    for (int t = threadIdx.x; t < 1024; t += 256) {
        int k = t >> 5, c = (t >> 2) & 7, w = t & 3;
        sW[k * 32 + (((c + (k >> 2)) & 7) << 2) + w] = eW2[t];
    }
    if (threadIdx.x < 32) sb[threadIdx.x] = eb2[threadIdx.x];
    __syncthreads();
    unsigned swa = (unsigned)__cvta_generic_to_shared(sW);
    unsigned sba = (unsigned)__cvta_generic_to_shared(sb);

    int lane = threadIdx.x & 31, warp = threadIdx.x >> 5;
    int qlane = lane & 3, qid = lane >> 2;
    int e0 = (blockIdx.x * 8 + warp) * 16 + qid * 2;
    int e1 = e0 + 1;
    bool v0 = e0 < E, v1 = e1 < E;
    int src0 = 0, tgt0 = 0, src1 = 0, tgt1 = 0;
    if (v1) {
        int2 s  = *(const int2*)(ei + e0);
        int2 t2 = *(const int2*)(ei + E + e0);
        src0 = s.x; src1 = s.y; tgt0 = t2.x; tgt1 = t2.y;
    } else if (v0) {
        src0 = ei[e0]; tgt0 = ei[E + e0];
    }

    const float4* Ar0 = (const float4*)(g_A + (size_t)tgt0 * 32);
    const float4* Br0 = (const float4*)(g_B + (size_t)src0 * 32);
    const float4* Ar1 = (const float4*)(g_A + (size_t)tgt1 * 32);
    const float4* Br1 = (const float4*)(g_B + (size_t)src1 * 32);
    float4 al0 = __ldg(Ar0 + qlane), ah0 = __ldg(Ar0 + 4 + qlane);
    float4 bl0 = __ldg(Br0 + qlane), bh0 = __ldg(Br0 + 4 + qlane);
    float4 al1 = __ldg(Ar1 + qlane), ah1 = __ldg(Ar1 + 4 + qlane);
    float4 bl1 = __ldg(Br1 + qlane), bh1 = __ldg(Br1 + 4 + qlane);

    float u0[8], u1[8];
    u0[0] = fmaxf(al0.x + bl0.x, 0.f); u0[1] = fmaxf(al0.y + bl0.y, 0.f);
    u0[2] = fmaxf(al0.z + bl0.z, 0.f); u0[3] = fmaxf(al0.w + bl0.w, 0.f);
    u0[4] = fmaxf(ah0.x + bh0.x, 0.f); u0[5] = fmaxf(ah0.y + bh0.y, 0.f);
    u0[6] = fmaxf(ah0.z + bh0.z, 0.f); u0[7] = fmaxf(ah0.w + bh0.w, 0.f);
    u1[0] = fmaxf(al1.x + bl1.x, 0.f); u1[1] = fmaxf(al1.y + bl1.y, 0.f);
    u1[2] = fmaxf(al1.z + bl1.z, 0.f); u1[3] = fmaxf(al1.w + bl1.w, 0.f);
    u1[4] = fmaxf(ah1.x + bh1.x, 0.f); u1[5] = fmaxf(ah1.y + bh1.y, 0.f);
    u1[6] = fmaxf(ah1.z + bh1.z, 0.f); u1[7] = fmaxf(ah1.w + bh1.w, 0.f);

    ull acc0[16], acc1[16];
    #pragma unroll
    for (int i = 0; i < 16; i++) { acc0[i] = 0ull; acc1[i] = 0ull; }

    #pragma unroll
    for (int kk = 0; kk < 8; kk++) {
        int k = qlane * 4 + (kk & 3) + ((kk & 4) << 2);   // +16 for kk>=4
        unsigned rot = (unsigned)(qlane + (kk & 4));       // = k>>2
        unsigned rowa = swa + (unsigned)k * 128u;
        ull up0 = pack2(u0[kk], u0[kk]);
        ull up1 = pack2(u1[kk], u1[kk]);
        #pragma unroll
        for (int q = 0; q < 8; q++) {
            unsigned phys = (unsigned)(q + rot) & 7u;
            ull w0, w1;
            lds_pair(rowa + phys * 16u, w0, w1);
            fma2(acc0[2*q],   up0, w0);
            fma2(acc0[2*q+1], up0, w1);
            fma2(acc1[2*q],   up1, w0);
            fma2(acc1[2*q+1], up1, w1);
        }
    }

    ull t4a[4], t4b[4];
    quad_rs(acc0, qlane, t4a);
    quad_rs(acc1, qlane, t4b);

    ull bb0, bb1, bb2, bb3;
    lds_pair(sba + (unsigned)qlane * 32u, bb0, bb1);
    lds_pair(sba + (unsigned)qlane * 32u + 16u, bb2, bb3);
    t4a[0] = addp(t4a[0], bb0); t4a[1] = addp(t4a[1], bb1);
    t4a[2] = addp(t4a[2], bb2); t4a[3] = addp(t4a[3], bb3);
    t4b[0] = addp(t4b[0], bb0); t4b[1] = addp(t4b[1], bb1);
    t4b[2] = addp(t4b[2], bb2); t4b[3] = addp(t4b[3], bb3);

    float m[8];
    if (v0) {
        unpack2(t4a[0], m[0], m[1]); unpack2(t4a[1], m[2], m[3]);
        unpack2(t4a[2], m[4], m[5]); unpack2(t4a[3], m[6], m[7]);
        float* dst = g_sumh + (size_t)tgt0 * 32 + qlane * 8;
        red4(dst,     fmaxf(m[0],0.f), fmaxf(m[1],0.f), fmaxf(m[2],0.f), fmaxf(m[3],0.f));
        red4(dst + 4, fmaxf(m[4],0.f), fmaxf(m[5],0.f), fmaxf(m[6],0.f), fmaxf(m[7],0.f));
        if (qlane == 0) redf(&g_cnt[tgt0], 1.0f);
    }
    if (v1) {
        unpack2(t4b[0], m[0], m[1]); unpack2(t4b[1], m[2], m[3]);
        unpack2(t4b[2], m[4], m[5]); unpack2(t4b[3], m[6], m[7]);
        float* dst = g_sumh + (size_t)tgt1 * 32 + qlane * 8;
        red4(dst,     fmaxf(m[0],0.f), fmaxf(m[1],0.f), fmaxf(m[2],0.f), fmaxf(m[3],0.f));
        red4(dst + 4, fmaxf(m[4],0.f), fmaxf(m[5],0.f), fmaxf(m[6],0.f), fmaxf(m[7],0.f));
        if (qlane == 0) redf(&g_cnt[tgt1], 1.0f);
    }
}

// ---- K4: per-node mid (mean, heads, reparam, decoder layer-1 split) ----
__global__ void k_mid(const float* __restrict__ mW, const float* __restrict__ mb,
                      const float* __restrict__ vW, const float* __restrict__ vb,
                      const float* __restrict__ dW1, const float* __restrict__ db1,
                      const float* __restrict__ eps2,
                      float* __restrict__ out_mu, float* __restrict__ out_lv, int n) {
    __shared__ float smW[64], svW[64], sWd[64], sWb[64], sdb1[32], smb[2], svb[2];
    int t = threadIdx.x;
    if (t < 64) { smW[t] = mW[t]; svW[t] = vW[t]; }
    if (t < 32) {
        sdb1[t] = db1[t];
        sWd[t]      = dW1[t]      - dW1[64 + t];
        sWd[32 + t] = dW1[32 + t] - dW1[96 + t];
        sWb[t]      = dW1[64 + t];
        sWb[32 + t] = dW1[96 + t];
    }
    if (t < 2) { smb[t] = mb[t]; svb[t] = vb[t]; }
    __syncthreads();
    for (int i = blockIdx.x * blockDim.x + t; i < n; i += gridDim.x * blockDim.x) {
        const float4* hr = (const float4*)(g_sumh + (size_t)i * 32);
        float inv = 1.0f / fmaxf(g_cnt[i], 1.0f);
        float h[32];
        #pragma unroll
        for (int q = 0; q < 8; q++) {
            float4 v = hr[q];
            h[4*q]   = v.x * inv; h[4*q+1] = v.y * inv;
            h[4*q+2] = v.z * inv; h[4*q+3] = v.w * inv;
        }
        float mu0 = smb[0], mu1 = smb[1], lv0 = svb[0], lv1 = svb[1];
        #pragma unroll
        for (int o = 0; o < 32; o++) {
            mu0 += h[o] * smW[2*o]; mu1 += h[o] * smW[2*o+1];
            lv0 += h[o] * svW[2*o]; lv1 += h[o] * svW[2*o+1];
        }
        float2 ep = ((const float2*)eps2)[i];
        float z0 = mu0 + ep.x * expf(0.5f * lv0);
        float z1 = mu1 + ep.y * expf(0.5f * lv1);
        ((float2*)out_mu)[i] = make_float2(mu0, mu1);
        ((float2*)out_lv)[i] = make_float2(lv0, lv1);
        float a[32], b[32];
        #pragma unroll
        for (int o = 0; o < 32; o++) {
            a[o] = sdb1[o] + z0 * sWd[o] + z1 * sWd[32 + o];
            b[o] = z0 * sWb[o] + z1 * sWb[32 + o];
        }
        float4* Ao = (float4*)(g_A + (size_t)i * 32);
        float4* Bo = (float4*)(g_B + (size_t)i * 32);
        #pragma unroll
        for (int q = 0; q < 8; q++) {
            Ao[q] = make_float4(a[4*q], a[4*q+1], a[4*q+2], a[4*q+3]);
            Bo[q] = make_float4(b[4*q], b[4*q+1], b[4*q+2], b[4*q+3]);
        }
    }
}

// ===================== quad-cooperative decoder edge pass =====================
__global__ void __launch_bounds__(256) k_dec(const int* __restrict__ ei,
                                             const float* __restrict__ dW2,
                                             const float* __restrict__ db2,
                                             const float* __restrict__ dW3,
                                             const float* __restrict__ db3, int E) {
    __shared__ __align__(16) float sW[1024];
    __shared__ __align__(16) float sW3[128];
    __shared__ __align__(16) float sb[32];
    __shared__ __align__(16) float sb3[4];
    for (int t = threadIdx.x; t < 1024; t += 256) {
        int k = t >> 5, c = (t >> 2) & 7, w = t & 3;
        sW[k * 32 + (((c + (k >> 2)) & 7) << 2) + w] = dW2[t];
    }
    if (threadIdx.x < 128) {
        int o = threadIdx.x >> 2, w = threadIdx.x & 3;
        sW3[((4 * (o & 7) + (o >> 3)) << 2) + w] = dW3[threadIdx.x];  // swizzled rows
    }
    if (threadIdx.x < 32) sb[threadIdx.x] = db2[threadIdx.x];
    if (threadIdx.x < 4)  sb3[threadIdx.x] = db3[threadIdx.x];
    __syncthreads();
    unsigned swa  = (unsigned)__cvta_generic_to_shared(sW);
    unsigned sw3a = (unsigned)__cvta_generic_to_shared(sW3);
    unsigned sba  = (unsigned)__cvta_generic_to_shared(sb);
    unsigned sb3a = (unsigned)__cvta_generic_to_shared(sb3);

    int lane = threadIdx.x & 31, warp = threadIdx.x >> 5;
    int qlane = lane & 3, qid = lane >> 2;
    int e0 = (blockIdx.x * 8 + warp) * 16 + qid * 2;
    int e1 = e0 + 1;
    bool v0 = e0 < E, v1 = e1 < E;
    int src0 = 0, tgt0 = 0, src1 = 0, tgt1 = 0;
    if (v1) {
        int2 s  = *(const int2*)(ei + e0);
        int2 t2 = *(const int2*)(ei + E + e0);
        src0 = s.x; src1 = s.y; tgt0 = t2.x; tgt1 = t2.y;
    } else if (v0) {
        src0 = ei[e0]; tgt0 = ei[E + e0];
    }

    const float4* Ar0 = (const float4*)(g_A + (size_t)tgt0 * 32);
    const float4* Br0 = (const float4*)(g_B + (size_t)src0 * 32);
    const float4* Ar1 = (const float4*)(g_A + (size_t)tgt1 * 32);
    const float4* Br1 = (const float4*)(g_B + (size_t)src1 * 32);
    float4 al0 = __ldg(Ar0 + qlane), ah0 = __ldg(Ar0 + 4 + qlane);
    float4 bl0 = __ldg(Br0 + qlane), bh0 = __ldg(Br0 + 4 + qlane);
    float4 al1 = __ldg(Ar1 + qlane), ah1 = __ldg(Ar1 + 4 + qlane);
    float4 bl1 = __ldg(Br1 + qlane), bh1 = __ldg(Br1 + 4 + qlane);

    float u0[8], u1[8];
    u0[0] = fmaxf(al0.x + bl0.x, 0.f); u0[1] = fmaxf(al0.y + bl0.y, 0.f);
    u0[2] = fmaxf(al0.z + bl0.z, 0.f); u0[3] = fmaxf(al0.w + bl0.w, 0.f);
    u0[4] = fmaxf(ah0.x + bh0.x, 0.f); u0[5] = fmaxf(ah0.y + bh0.y, 0.f);
    u0[6] = fmaxf(ah0.z + bh0.z, 0.f); u0[7] = fmaxf(ah0.w + bh0.w, 0.f);
    u1[0] = fmaxf(al1.x + bl1.x, 0.f); u1[1] = fmaxf(al1.y + bl1.y, 0.f);
    u1[2] = fmaxf(al1.z + bl1.z, 0.f); u1[3] = fmaxf(al1.w + bl1.w, 0.f);
    u1[4] = fmaxf(ah1.x + bh1.x, 0.f); u1[5] = fmaxf(ah1.y + bh1.y, 0.f);
    u1[6] = fmaxf(ah1.z + bh1.z, 0.f); u1[7] = fmaxf(ah1.w + bh1.w, 0.f);

    ull acc0[16], acc1[16];
    #pragma unroll
    for (int i = 0; i < 16; i++) { acc0[i] = 0ull; acc1[i] = 0ull; }

    #pragma unroll
    for (int kk = 0; kk < 8; kk++) {
        int k = qlane * 4 + (kk & 3) + ((kk & 4) << 2);
        unsigned rot = (unsigned)(qlane + (kk & 4));
        unsigned rowa = swa + (unsigned)k * 128u;
        ull up0 = pack2(u0[kk], u0[kk]);
        ull up1 = pack2(u1[kk], u1[kk]);
        #pragma unroll
        for (int q = 0; q < 8; q++) {
            unsigned phys = (unsigned)(q + rot) & 7u;
            ull w0, w1;
            lds_pair(rowa + phys * 16u, w0, w1);
            fma2(acc0[2*q],   up0, w0);
            fma2(acc0[2*q+1], up0, w1);
            fma2(acc1[2*q],   up1, w0);
            fma2(acc1[2*q+1], up1, w1);
        }
    }

    ull t4a[4], t4b[4];
    quad_rs(acc0, qlane, t4a);
    quad_rs(acc1, qlane, t4b);

    ull bb0, bb1, bb2, bb3;
    lds_pair(sba + (unsigned)qlane * 32u, bb0, bb1);
    lds_pair(sba + (unsigned)qlane * 32u + 16u, bb2, bb3);
    t4a[0] = addp(t4a[0], bb0); t4a[1] = addp(t4a[1], bb1);
    t4a[2] = addp(t4a[2], bb2); t4a[3] = addp(t4a[3], bb3);
    t4b[0] = addp(t4b[0], bb0); t4b[1] = addp(t4b[1], bb1);
    t4b[2] = addp(t4b[2], bb2); t4b[3] = addp(t4b[3], bb3);

    float va[8], vb_[8];
    unpack2(t4a[0], va[0], va[1]); unpack2(t4a[1], va[2], va[3]);
    unpack2(t4a[2], va[4], va[5]); unpack2(t4a[3], va[6], va[7]);
    unpack2(t4b[0], vb_[0], vb_[1]); unpack2(t4b[1], vb_[2], vb_[3]);
    unpack2(t4b[2], vb_[4], vb_[5]); unpack2(t4b[3], vb_[6], vb_[7]);
    #pragma unroll
    for (int i = 0; i < 8; i++) { va[i] = fmaxf(va[i], 0.f); vb_[i] = fmaxf(vb_[i], 0.f); }

    // layer-3: lane owns outputs o = qlane*8 + i; W3 row o at swizzled slot (4*i + qlane)
    ull oc0a = 0, oc1a = 0, oc0b = 0, oc1b = 0;
    #pragma unroll
    for (int i = 0; i < 8; i++) {
        ull w0, w1;
        lds_pair(sw3a + (unsigned)((4 * i + qlane) * 16), w0, w1);
        ull vp0 = pack2(va[i], va[i]);
        ull vp1 = pack2(vb_[i], vb_[i]);
        fma2(oc0a, vp0, w0); fma2(oc1a, vp0, w1);
        fma2(oc0b, vp1, w0); fma2(oc1b, vp1, w1);
    }
    // quad allreduce (4 floats per edge)
    oc0a = addp(oc0a, shflx(oc0a, 1)); oc0a = addp(oc0a, shflx(oc0a, 2));
    oc1a = addp(oc1a, shflx(oc1a, 1)); oc1a = addp(oc1a, shflx(oc1a, 2));
    oc0b = addp(oc0b, shflx(oc0b, 1)); oc0b = addp(oc0b, shflx(oc0b, 2));
    oc1b = addp(oc1b, shflx(oc1b, 1)); oc1b = addp(oc1b, shflx(oc1b, 2));

    if (qlane == 0) {
        ull b0, b1;
        lds_pair(sb3a, b0, b1);
        if (v0) {
            ull r0 = addp(oc0a, b0), r1 = addp(oc1a, b1);
            float f0, f1, f2, f3;
            unpack2(r0, f0, f1); unpack2(r1, f2, f3);
            red4(g_sumout + (size_t)tgt0 * 4, f0, f1, f2, f3);
        }
        if (v1) {
            ull r0 = addp(oc0b, b0), r1 = addp(oc1b, b1);
            float f0, f1, f2, f3;
            unpack2(r0, f0, f1); unpack2(r1, f2, f3);
            red4(g_sumout + (size_t)tgt1 * 4, f0, f1, f2, f3);
        }
    }
}

// ---- K6: per-node output mean ----
__global__ void k_out(float* __restrict__ out, int n) {
    for (int i = blockIdx.x * blockDim.x + threadIdx.x; i < n; i += gridDim.x * blockDim.x) {
        float inv = 1.0f / fmaxf(g_cnt[i], 1.0f);
        float4 s = ((const float4*)g_sumout)[i];
        ((float4*)out)[i] = make_float4(s.x * inv, s.y * inv, s.z * inv, s.w * inv);
    }
}

extern "C" void kernel_launch(void* const* d_in, const int* in_sizes, int n_in,
                              void* d_out, int out_size) {
    const float* x     = (const float*)d_in[0];
    const int*   ei    = (const int*)d_in[1];
    const float* eps   = (const float*)d_in[2];
    const float* gamma = (const float*)d_in[3];
    const float* beta  = (const float*)d_in[4];
    const float* eW1   = (const float*)d_in[5];
    const float* eb1   = (const float*)d_in[6];
    const float* eW2   = (const float*)d_in[7];
    const float* eb2   = (const float*)d_in[8];
    const float* mW    = (const float*)d_in[9];
    const float* mb    = (const float*)d_in[10];
    const float* vW    = (const float*)d_in[11];
    const float* vb    = (const float*)d_in[12];
    const float* dW1   = (const float*)d_in[13];
    const float* db1   = (const float*)d_in[14];
    const float* dW2   = (const float*)d_in[15];
    const float* db2   = (const float*)d_in[16];
    const float* dW3   = (const float*)d_in[17];
    const float* db3   = (const float*)d_in[18];

    int n = in_sizes[0] / 4;
    int E = in_sizes[1] / 2;

    float* out    = (float*)d_out;
    float* out_mu = out + (size_t)n * 4;
    float* out_lv = out + (size_t)n * 6;

    int nb = (n + 255) / 256;
    int eb = (E + 127) / 128;   // 128 edges per block (8 warps x 16 edges)

    k_zero<<<512, 256>>>(n);
    k_stats<<<256, 256>>>((const float4*)x, n);
    k_pre<<<nb, 256>>>((const float4*)x, gamma, beta, eW1, eb1, n, 1.0f / (float)n);
    k_enc<<<eb, 256>>>(ei, eW2, eb2, E);
    k_mid<<<nb, 256>>>(mW, mb, vW, vb, dW1, db1, eps, out_mu, out_lv, n);
    k_dec<<<eb, 256>>>(ei, dW2, db2, dW3, db3, E);
    k_out<<<nb, 256>>>(out, n);
}

// round 6
// speedup vs baseline: 1.2697x; 1.1204x over previous
#include <cuda_runtime.h>
#include <math.h>

#define N_MAX 100000
typedef unsigned long long ull;

// ---- scratch (static __device__ arrays; allocation-free) ----
__device__ __align__(16) float g_A[N_MAX * 32];
__device__ __align__(16) float g_B[N_MAX * 32];
__device__ __align__(16) float g_sumenc[N_MAX * 4];   // per-node sum of msg @ [mW|vW]
__device__ __align__(16) float g_cnt[N_MAX];
__device__ __align__(16) float g_sumout[N_MAX * 4];
__device__ __align__(16) float g_stats[8];

// ---- f32x2 / LDS / red helpers ----
__device__ __forceinline__ ull pack2(float x, float y) {
    ull r; asm("mov.b64 %0, {%1,%2};" : "=l"(r) : "f"(x), "f"(y)); return r;
}
__device__ __forceinline__ void unpack2(ull v, float& x, float& y) {
    asm("mov.b64 {%0,%1}, %2;" : "=f"(x), "=f"(y) : "l"(v));
}
__device__ __forceinline__ void fma2(ull& d, ull a, ull b) {
    asm("fma.rn.f32x2 %0, %1, %2, %3;" : "=l"(d) : "l"(a), "l"(b), "l"(d));
}
__device__ __forceinline__ ull addp(ull a, ull b) {
    ull r; asm("add.rn.f32x2 %0, %1, %2;" : "=l"(r) : "l"(a), "l"(b)); return r;
}
__device__ __forceinline__ void lds_pair(unsigned addr, ull& a, ull& b) {
    asm volatile("ld.shared.v2.u64 {%0,%1}, [%2];" : "=l"(a), "=l"(b) : "r"(addr));
}
__device__ __forceinline__ void red4(float* p, float a, float b, float c, float d) {
    asm volatile("red.global.add.v4.f32 [%0], {%1,%2,%3,%4};"
                 :: "l"(p), "f"(a), "f"(b), "f"(c), "f"(d) : "memory");
}
__device__ __forceinline__ void redf(float* p, float v) {
    asm volatile("red.global.add.f32 [%0], %1;" :: "l"(p), "f"(v) : "memory");
}
__device__ __forceinline__ ull shflx(ull v, int m) {
    return __shfl_xor_sync(0xffffffffu, v, m);
}

// quad reduce-scatter: acc[16] (32 outputs, k-partial) -> t4[4] (lane owns outputs [qlane*8, qlane*8+8))
__device__ __forceinline__ void quad_rs(const ull acc[16], int qlane, ull t4[4]) {
    ull t8[8];
    bool hi2 = (qlane & 2) != 0;
    #pragma unroll
    for (int i = 0; i < 8; i++) {
        ull sel  = hi2 ? acc[i]     : acc[i + 8];
        ull keep = hi2 ? acc[i + 8] : acc[i];
        t8[i] = addp(keep, shflx(sel, 2));
    }
    bool hi1 = (qlane & 1) != 0;
    #pragma unroll
    for (int i = 0; i < 4; i++) {
        ull sel  = hi1 ? t8[i]     : t8[i + 4];
        ull keep = hi1 ? t8[i + 4] : t8[i];
        t4[i] = addp(keep, shflx(sel, 1));
    }
}

// ---- K0: zero accumulators ----
__global__ void k_zero(int n) {
    int i = blockIdx.x * blockDim.x + threadIdx.x;
    int stride = gridDim.x * blockDim.x;
    float4 z = make_float4(0.f, 0.f, 0.f, 0.f);
    float4* a = (float4*)g_sumenc; int na = n;
    for (int t = i; t < na; t += stride) a[t] = z;
    float4* b = (float4*)g_sumout; int nb = n;
    for (int t = i; t < nb; t += stride) b[t] = z;
    float4* c = (float4*)g_cnt;    int nc = n >> 2;
    for (int t = i; t < nc; t += stride) c[t] = z;
    if (i < 8) g_stats[i] = 0.f;
}

// ---- K1: batchnorm statistics ----
__global__ void k_stats(const float4* __restrict__ x, int n) {
    float sx = 0, sy = 0, sz = 0, sw = 0, qx = 0, qy = 0, qz = 0, qw = 0;
    for (int i = blockIdx.x * blockDim.x + threadIdx.x; i < n; i += gridDim.x * blockDim.x) {
        float4 v = x[i];
        sx += v.x; sy += v.y; sz += v.z; sw += v.w;
        qx += v.x * v.x; qy += v.y * v.y; qz += v.z * v.z; qw += v.w * v.w;
    }
    #pragma unroll
    for (int off = 16; off; off >>= 1) {
        sx += __shfl_down_sync(0xffffffffu, sx, off);
        sy += __shfl_down_sync(0xffffffffu, sy, off);
        sz += __shfl_down_sync(0xffffffffu, sz, off);
        sw += __shfl_down_sync(0xffffffffu, sw, off);
        qx += __shfl_down_sync(0xffffffffu, qx, off);
        qy += __shfl_down_sync(0xffffffffu, qy, off);
        qz += __shfl_down_sync(0xffffffffu, qz, off);
        qw += __shfl_down_sync(0xffffffffu, qw, off);
    }
    if ((threadIdx.x & 31) == 0) {
        atomicAdd(&g_stats[0], sx); atomicAdd(&g_stats[1], sy);
        atomicAdd(&g_stats[2], sz); atomicAdd(&g_stats[3], sw);
        atomicAdd(&g_stats[4], qx); atomicAdd(&g_stats[5], qy);
        atomicAdd(&g_stats[6], qz); atomicAdd(&g_stats[7], qw);
    }
}

// ---- K2: BN + encoder layer-1 split (A = xn@(W1a-W1b)+b1, B = xn@W1b) ----
__global__ void k_pre(const float4* __restrict__ x,
                      const float* __restrict__ gamma, const float* __restrict__ beta,
                      const float* __restrict__ eW1, const float* __restrict__ eb1,
                      int n, float invN) {
    __shared__ float sWd[128], sWb[128], sb1[32], sScale[4], sShift[4];
    int t = threadIdx.x;
    if (t < 128) {
        int c = t >> 5, o = t & 31;
        float wa = eW1[c * 32 + o], wb = eW1[(4 + c) * 32 + o];
        sWd[t] = wa - wb; sWb[t] = wb;
    }
    if (t < 32) sb1[t] = eb1[t];
    if (t < 4) {
        float m = g_stats[t] * invN;
        float v = g_stats[4 + t] * invN - m * m;
        float s = rsqrtf(v + 1e-5f) * gamma[t];
        sScale[t] = s; sShift[t] = beta[t] - m * s;
    }
    __syncthreads();
    for (int i = blockIdx.x * blockDim.x + t; i < n; i += gridDim.x * blockDim.x) {
        float4 xv = x[i];
        float xn[4];
        xn[0] = xv.x * sScale[0] + sShift[0];
        xn[1] = xv.y * sScale[1] + sShift[1];
        xn[2] = xv.z * sScale[2] + sShift[2];
        xn[3] = xv.w * sScale[3] + sShift[3];
        float a[32], b[32];
        #pragma unroll
        for (int o = 0; o < 32; o++) {
            float av = sb1[o], bv = 0.f;
            #pragma unroll
            for (int c = 0; c < 4; c++) {
                av += xn[c] * sWd[c * 32 + o];
                bv += xn[c] * sWb[c * 32 + o];
            }
            a[o] = av; b[o] = bv;
        }
        float4* Ao = (float4*)(g_A + (size_t)i * 32);
        float4* Bo = (float4*)(g_B + (size_t)i * 32);
        #pragma unroll
        for (int q = 0; q < 8; q++) {
            Ao[q] = make_float4(a[4*q], a[4*q+1], a[4*q+2], a[4*q+3]);
            Bo[q] = make_float4(b[4*q], b[4*q+1], b[4*q+2], b[4*q+3]);
        }
    }
}

// ===================== encoder edge pass (quad-coop, projected epilogue) =====================
// warp = 8 quads; quad handles 2 edges; lane owns k in {4*qlane+j, 16+4*qlane+j}
// epilogue: msg = relu(relu(u)@W2+b2); scatter msg@[mW|vW] (4 floats) via one red4
__global__ void __launch_bounds__(128, 5) k_enc(const int* __restrict__ ei,
                                                const float* __restrict__ eW2,
                                                const float* __restrict__ eb2,
                                                const float* __restrict__ mW,
                                                const float* __restrict__ vW, int E) {
    __shared__ __align__(16) float sW[1024];
    __shared__ __align__(16) float sP[128];   // row o: {mW[o][0], mW[o][1], vW[o][0], vW[o][1]}, swizzled
    __shared__ __align__(16) float sb[32];
    for (int t = threadIdx.x; t < 1024; t += 128) {
        int k = t >> 5, c = (t >> 2) & 7, w = t & 3;
        sW[k * 32 + (((c + (k >> 2)) & 7) << 2) + w] = eW2[t];
    }
    if (threadIdx.x < 128) {
        int o = threadIdx.x >> 2, w = threadIdx.x & 3;
        float val = (w < 2) ? mW[o * 2 + w] : vW[o * 2 + (w - 2)];
        sP[(((o >> 3) + ((o & 7) << 2)) << 2) + w] = val;   // slot = qlane + 4*i
    }
    if (threadIdx.x < 32) sb[threadIdx.x] = eb2[threadIdx.x];
    __syncthreads();
    unsigned swa = (unsigned)__cvta_generic_to_shared(sW);
    unsigned spa = (unsigned)__cvta_generic_to_shared(sP);
    unsigned sba = (unsigned)__cvta_generic_to_shared(sb);

    int lane = threadIdx.x & 31, warp = threadIdx.x >> 5;
    int qlane = lane & 3, qid = lane >> 2;
    int e0 = (blockIdx.x * 4 + warp) * 16 + qid * 2;
    int e1 = e0 + 1;
    bool v0 = e0 < E, v1 = e1 < E;
    int src0 = 0, tgt0 = 0, src1 = 0, tgt1 = 0;
    if (v1) {
        int2 s  = *(const int2*)(ei + e0);
        int2 t2 = *(const int2*)(ei + E + e0);
        src0 = s.x; src1 = s.y; tgt0 = t2.x; tgt1 = t2.y;
    } else if (v0) {
        src0 = ei[e0]; tgt0 = ei[E + e0];
    }

    const float4* Ar0 = (const float4*)(g_A + (size_t)tgt0 * 32);
    const float4* Br0 = (const float4*)(g_B + (size_t)src0 * 32);
    const float4* Ar1 = (const float4*)(g_A + (size_t)tgt1 * 32);
    const float4* Br1 = (const float4*)(g_B + (size_t)src1 * 32);
    float4 al0 = __ldg(Ar0 + qlane), ah0 = __ldg(Ar0 + 4 + qlane);
    float4 bl0 = __ldg(Br0 + qlane), bh0 = __ldg(Br0 + 4 + qlane);
    float4 al1 = __ldg(Ar1 + qlane), ah1 = __ldg(Ar1 + 4 + qlane);
    float4 bl1 = __ldg(Br1 + qlane), bh1 = __ldg(Br1 + 4 + qlane);

    float u0[8], u1[8];
    u0[0] = fmaxf(al0.x + bl0.x, 0.f); u0[1] = fmaxf(al0.y + bl0.y, 0.f);
    u0[2] = fmaxf(al0.z + bl0.z, 0.f); u0[3] = fmaxf(al0.w + bl0.w, 0.f);
    u0[4] = fmaxf(ah0.x + bh0.x, 0.f); u0[5] = fmaxf(ah0.y + bh0.y, 0.f);
    u0[6] = fmaxf(ah0.z + bh0.z, 0.f); u0[7] = fmaxf(ah0.w + bh0.w, 0.f);
    u1[0] = fmaxf(al1.x + bl1.x, 0.f); u1[1] = fmaxf(al1.y + bl1.y, 0.f);
    u1[2] = fmaxf(al1.z + bl1.z, 0.f); u1[3] = fmaxf(al1.w + bl1.w, 0.f);
    u1[4] = fmaxf(ah1.x + bh1.x, 0.f); u1[5] = fmaxf(ah1.y + bh1.y, 0.f);
    u1[6] = fmaxf(ah1.z + bh1.z, 0.f); u1[7] = fmaxf(ah1.w + bh1.w, 0.f);

    ull acc0[16], acc1[16];
    #pragma unroll
    for (int i = 0; i < 16; i++) { acc0[i] = 0ull; acc1[i] = 0ull; }

    #pragma unroll
    for (int kk = 0; kk < 8; kk++) {
        int k = qlane * 4 + (kk & 3) + ((kk & 4) << 2);
        unsigned rot = (unsigned)(qlane + (kk & 4));
        unsigned rowa = swa + (unsigned)k * 128u;
        ull up0 = pack2(u0[kk], u0[kk]);
        ull up1 = pack2(u1[kk], u1[kk]);
        #pragma unroll
        for (int q = 0; q < 8; q++) {
            unsigned phys = (unsigned)(q + rot) & 7u;
            ull w0, w1;
            lds_pair(rowa + phys * 16u, w0, w1);
            fma2(acc0[2*q],   up0, w0);
            fma2(acc0[2*q+1], up0, w1);
            fma2(acc1[2*q],   up1, w0);
            fma2(acc1[2*q+1], up1, w1);
        }
    }

    ull t4a[4], t4b[4];
    quad_rs(acc0, qlane, t4a);
    quad_rs(acc1, qlane, t4b);

    ull bb0, bb1, bb2, bb3;
    lds_pair(sba + (unsigned)qlane * 32u, bb0, bb1);
    lds_pair(sba + (unsigned)qlane * 32u + 16u, bb2, bb3);
    t4a[0] = addp(t4a[0], bb0); t4a[1] = addp(t4a[1], bb1);
    t4a[2] = addp(t4a[2], bb2); t4a[3] = addp(t4a[3], bb3);
    t4b[0] = addp(t4b[0], bb0); t4b[1] = addp(t4b[1], bb1);
    t4b[2] = addp(t4b[2], bb2); t4b[3] = addp(t4b[3], bb3);

    float ma[8], mb_[8];
    unpack2(t4a[0], ma[0], ma[1]); unpack2(t4a[1], ma[2], ma[3]);
    unpack2(t4a[2], ma[4], ma[5]); unpack2(t4a[3], ma[6], ma[7]);
    unpack2(t4b[0], mb_[0], mb_[1]); unpack2(t4b[1], mb_[2], mb_[3]);
    unpack2(t4b[2], mb_[4], mb_[5]); unpack2(t4b[3], mb_[6], mb_[7]);
    #pragma unroll
    for (int i = 0; i < 8; i++) { ma[i] = fmaxf(ma[i], 0.f); mb_[i] = fmaxf(mb_[i], 0.f); }

    // project: p = msg @ [mW | vW]  (lane owns outputs o = qlane*8 + i)
    ull pa01 = 0, pa23 = 0, pb01 = 0, pb23 = 0;
    #pragma unroll
    for (int i = 0; i < 8; i++) {
        ull w0, w1;
        lds_pair(spa + (unsigned)((qlane + 4 * i) * 16), w0, w1);
        ull va = pack2(ma[i], ma[i]);
        ull vb2 = pack2(mb_[i], mb_[i]);
        fma2(pa01, va, w0); fma2(pa23, va, w1);
        fma2(pb01, vb2, w0); fma2(pb23, vb2, w1);
    }
    pa01 = addp(pa01, shflx(pa01, 1)); pa01 = addp(pa01, shflx(pa01, 2));
    pa23 = addp(pa23, shflx(pa23, 1)); pa23 = addp(pa23, shflx(pa23, 2));
    pb01 = addp(pb01, shflx(pb01, 1)); pb01 = addp(pb01, shflx(pb01, 2));
    pb23 = addp(pb23, shflx(pb23, 1)); pb23 = addp(pb23, shflx(pb23, 2));

    if (qlane == 0) {
        if (v0) {
            float f0, f1, f2, f3;
            unpack2(pa01, f0, f1); unpack2(pa23, f2, f3);
            red4(g_sumenc + (size_t)tgt0 * 4, f0, f1, f2, f3);
            redf(&g_cnt[tgt0], 1.0f);
        }
        if (v1) {
            float f0, f1, f2, f3;
            unpack2(pb01, f0, f1); unpack2(pb23, f2, f3);
            red4(g_sumenc + (size_t)tgt1 * 4, f0, f1, f2, f3);
            redf(&g_cnt[tgt1], 1.0f);
        }
    }
}

// ---- K4: per-node mid: mu/lv from projected sums, reparam z, decoder layer-1 split ----
__global__ void k_mid(const float* __restrict__ mb, const float* __restrict__ vb,
                      const float* __restrict__ dW1, const float* __restrict__ db1,
                      const float* __restrict__ eps2,
                      float* __restrict__ out_mu, float* __restrict__ out_lv, int n) {
    __shared__ float sWd[64], sWb[64], sdb1[32], smb[2], svb[2];
    int t = threadIdx.x;
    if (t < 32) {
        sdb1[t] = db1[t];
        sWd[t]      = dW1[t]      - dW1[64 + t];
        sWd[32 + t] = dW1[32 + t] - dW1[96 + t];
        sWb[t]      = dW1[64 + t];
        sWb[32 + t] = dW1[96 + t];
    }
    if (t < 2) { smb[t] = mb[t]; svb[t] = vb[t]; }
    __syncthreads();
    for (int i = blockIdx.x * blockDim.x + t; i < n; i += gridDim.x * blockDim.x) {
        float4 s = ((const float4*)g_sumenc)[i];
        float inv = 1.0f / fmaxf(g_cnt[i], 1.0f);
        float mu0 = s.x * inv + smb[0];
        float mu1 = s.y * inv + smb[1];
        float lv0 = s.z * inv + svb[0];
        float lv1 = s.w * inv + svb[1];
        float2 ep = ((const float2*)eps2)[i];
        float z0 = mu0 + ep.x * expf(0.5f * lv0);
        float z1 = mu1 + ep.y * expf(0.5f * lv1);
        ((float2*)out_mu)[i] = make_float2(mu0, mu1);
        ((float2*)out_lv)[i] = make_float2(lv0, lv1);
        float a[32], b[32];
        #pragma unroll
        for (int o = 0; o < 32; o++) {
            a[o] = sdb1[o] + z0 * sWd[o] + z1 * sWd[32 + o];
            b[o] = z0 * sWb[o] + z1 * sWb[32 + o];
        }
        float4* Ao = (float4*)(g_A + (size_t)i * 32);
        float4* Bo = (float4*)(g_B + (size_t)i * 32);
        #pragma unroll
        for (int q = 0; q < 8; q++) {
            Ao[q] = make_float4(a[4*q], a[4*q+1], a[4*q+2], a[4*q+3]);
            Bo[q] = make_float4(b[4*q], b[4*q+1], b[4*q+2], b[4*q+3]);
        }
    }
}

// ===================== decoder edge pass (quad-coop) =====================
__global__ void __launch_bounds__(128, 5) k_dec(const int* __restrict__ ei,
                                                const float* __restrict__ dW2,
                                                const float* __restrict__ db2,
                                                const float* __restrict__ dW3,
                                                const float* __restrict__ db3, int E) {
    __shared__ __align__(16) float sW[1024];
    __shared__ __align__(16) float sW3[128];
    __shared__ __align__(16) float sb[32];
    __shared__ __align__(16) float sb3[4];
    for (int t = threadIdx.x; t < 1024; t += 128) {
        int k = t >> 5, c = (t >> 2) & 7, w = t & 3;
        sW[k * 32 + (((c + (k >> 2)) & 7) << 2) + w] = dW2[t];
    }
    if (threadIdx.x < 128) {
        int o = threadIdx.x >> 2, w = threadIdx.x & 3;
        sW3[((4 * (o & 7) + (o >> 3)) << 2) + w] = dW3[threadIdx.x];  // slot = 4*i + qlane
    }
    if (threadIdx.x < 32) sb[threadIdx.x] = db2[threadIdx.x];
    if (threadIdx.x < 4)  sb3[threadIdx.x] = db3[threadIdx.x];
    __syncthreads();
    unsigned swa  = (unsigned)__cvta_generic_to_shared(sW);
    unsigned sw3a = (unsigned)__cvta_generic_to_shared(sW3);
    unsigned sba  = (unsigned)__cvta_generic_to_shared(sb);
    unsigned sb3a = (unsigned)__cvta_generic_to_shared(sb3);

    int lane = threadIdx.x & 31, warp = threadIdx.x >> 5;
    int qlane = lane & 3, qid = lane >> 2;
    int e0 = (blockIdx.x * 4 + warp) * 16 + qid * 2;
    int e1 = e0 + 1;
    bool v0 = e0 < E, v1 = e1 < E;
    int src0 = 0, tgt0 = 0, src1 = 0, tgt1 = 0;
    if (v1) {
        int2 s  = *(const int2*)(ei + e0);
        int2 t2 = *(const int2*)(ei + E + e0);
        src0 = s.x; src1 = s.y; tgt0 = t2.x; tgt1 = t2.y;
    } else if (v0) {
        src0 = ei[e0]; tgt0 = ei[E + e0];
    }

    const float4* Ar0 = (const float4*)(g_A + (size_t)tgt0 * 32);
    const float4* Br0 = (const float4*)(g_B + (size_t)src0 * 32);
    const float4* Ar1 = (const float4*)(g_A + (size_t)tgt1 * 32);
    const float4* Br1 = (const float4*)(g_B + (size_t)src1 * 32);
    float4 al0 = __ldg(Ar0 + qlane), ah0 = __ldg(Ar0 + 4 + qlane);
    float4 bl0 = __ldg(Br0 + qlane), bh0 = __ldg(Br0 + 4 + qlane);
    float4 al1 = __ldg(Ar1 + qlane), ah1 = __ldg(Ar1 + 4 + qlane);
    float4 bl1 = __ldg(Br1 + qlane), bh1 = __ldg(Br1 + 4 + qlane);

    float u0[8], u1[8];
    u0[0] = fmaxf(al0.x + bl0.x, 0.f); u0[1] = fmaxf(al0.y + bl0.y, 0.f);
    u0[2] = fmaxf(al0.z + bl0.z, 0.f); u0[3] = fmaxf(al0.w + bl0.w, 0.f);
    u0[4] = fmaxf(ah0.x + bh0.x, 0.f); u0[5] = fmaxf(ah0.y + bh0.y, 0.f);
    u0[6] = fmaxf(ah0.z + bh0.z, 0.f); u0[7] = fmaxf(ah0.w + bh0.w, 0.f);
    u1[0] = fmaxf(al1.x + bl1.x, 0.f); u1[1] = fmaxf(al1.y + bl1.y, 0.f);
    u1[2] = fmaxf(al1.z + bl1.z, 0.f); u1[3] = fmaxf(al1.w + bl1.w, 0.f);
    u1[4] = fmaxf(ah1.x + bh1.x, 0.f); u1[5] = fmaxf(ah1.y + bh1.y, 0.f);
    u1[6] = fmaxf(ah1.z + bh1.z, 0.f); u1[7] = fmaxf(ah1.w + bh1.w, 0.f);

    ull acc0[16], acc1[16];
    #pragma unroll
    for (int i = 0; i < 16; i++) { acc0[i] = 0ull; acc1[i] = 0ull; }

    #pragma unroll
    for (int kk = 0; kk < 8; kk++) {
        int k = qlane * 4 + (kk & 3) + ((kk & 4) << 2);
        unsigned rot = (unsigned)(qlane + (kk & 4));
        unsigned rowa = swa + (unsigned)k * 128u;
        ull up0 = pack2(u0[kk], u0[kk]);
        ull up1 = pack2(u1[kk], u1[kk]);
        #pragma unroll
        for (int q = 0; q < 8; q++) {
            unsigned phys = (unsigned)(q + rot) & 7u;
            ull w0, w1;
            lds_pair(rowa + phys * 16u, w0, w1);
            fma2(acc0[2*q],   up0, w0);
            fma2(acc0[2*q+1], up0, w1);
            fma2(acc1[2*q],   up1, w0);
            fma2(acc1[2*q+1], up1, w1);
        }
    }

    ull t4a[4], t4b[4];
    quad_rs(acc0, qlane, t4a);
    quad_rs(acc1, qlane, t4b);

    ull bb0, bb1, bb2, bb3;
    lds_pair(sba + (unsigned)qlane * 32u, bb0, bb1);
    lds_pair(sba + (unsigned)qlane * 32u + 16u, bb2, bb3);
    t4a[0] = addp(t4a[0], bb0); t4a[1] = addp(t4a[1], bb1);
    t4a[2] = addp(t4a[2], bb2); t4a[3] = addp(t4a[3], bb3);
    t4b[0] = addp(t4b[0], bb0); t4b[1] = addp(t4b[1], bb1);
    t4b[2] = addp(t4b[2], bb2); t4b[3] = addp(t4b[3], bb3);

    float va[8], vb_[8];
    unpack2(t4a[0], va[0], va[1]); unpack2(t4a[1], va[2], va[3]);
    unpack2(t4a[2], va[4], va[5]); unpack2(t4a[3], va[6], va[7]);
    unpack2(t4b[0], vb_[0], vb_[1]); unpack2(t4b[1], vb_[2], vb_[3]);
    unpack2(t4b[2], vb_[4], vb_[5]); unpack2(t4b[3], vb_[6], vb_[7]);
    #pragma unroll
    for (int i = 0; i < 8; i++) { va[i] = fmaxf(va[i], 0.f); vb_[i] = fmaxf(vb_[i], 0.f); }

    // layer-3: lane owns outputs o = qlane*8 + i; W3 row o at swizzled slot (4*i + qlane)
    ull oc0a = 0, oc1a = 0, oc0b = 0, oc1b = 0;
    #pragma unroll
    for (int i = 0; i < 8; i++) {
        ull w0, w1;
        lds_pair(sw3a + (unsigned)((4 * i + qlane) * 16), w0, w1);
        ull vp0 = pack2(va[i], va[i]);
        ull vp1 = pack2(vb_[i], vb_[i]);
        fma2(oc0a, vp0, w0); fma2(oc1a, vp0, w1);
        fma2(oc0b, vp1, w0); fma2(oc1b, vp1, w1);
    }
    oc0a = addp(oc0a, shflx(oc0a, 1)); oc0a = addp(oc0a, shflx(oc0a, 2));
    oc1a = addp(oc1a, shflx(oc1a, 1)); oc1a = addp(oc1a, shflx(oc1a, 2));
    oc0b = addp(oc0b, shflx(oc0b, 1)); oc0b = addp(oc0b, shflx(oc0b, 2));
    oc1b = addp(oc1b, shflx(oc1b, 1)); oc1b = addp(oc1b, shflx(oc1b, 2));

    if (qlane == 0) {
        ull b0, b1;
        lds_pair(sb3a, b0, b1);
        if (v0) {
            ull r0 = addp(oc0a, b0), r1 = addp(oc1a, b1);
            float f0, f1, f2, f3;
            unpack2(r0, f0, f1); unpack2(r1, f2, f3);
            red4(g_sumout + (size_t)tgt0 * 4, f0, f1, f2, f3);
        }
        if (v1) {
            ull r0 = addp(oc0b, b0), r1 = addp(oc1b, b1);
            float f0, f1, f2, f3;
            unpack2(r0, f0, f1); unpack2(r1, f2, f3);
            red4(g_sumout + (size_t)tgt1 * 4, f0, f1, f2, f3);
        }
    }
}

// ---- K6: per-node output mean ----
__global__ void k_out(float* __restrict__ out, int n) {
    for (int i = blockIdx.x * blockDim.x + threadIdx.x; i < n; i += gridDim.x * blockDim.x) {
        float inv = 1.0f / fmaxf(g_cnt[i], 1.0f);
        float4 s = ((const float4*)g_sumout)[i];
        ((float4*)out)[i] = make_float4(s.x * inv, s.y * inv, s.z * inv, s.w * inv);
    }
}

extern "C" void kernel_launch(void* const* d_in, const int* in_sizes, int n_in,
                              void* d_out, int out_size) {
    const float* x     = (const float*)d_in[0];
    const int*   ei    = (const int*)d_in[1];
    const float* eps   = (const float*)d_in[2];
    const float* gamma = (const float*)d_in[3];
    const float* beta  = (const float*)d_in[4];
    const float* eW1   = (const float*)d_in[5];
    const float* eb1   = (const float*)d_in[6];
    const float* eW2   = (const float*)d_in[7];
    const float* eb2   = (const float*)d_in[8];
    const float* mW    = (const float*)d_in[9];
    const float* mb    = (const float*)d_in[10];
    const float* vW    = (const float*)d_in[11];
    const float* vb    = (const float*)d_in[12];
    const float* dW1   = (const float*)d_in[13];
    const float* db1   = (const float*)d_in[14];
    const float* dW2   = (const float*)d_in[15];
    const float* db2   = (const float*)d_in[16];
    const float* dW3   = (const float*)d_in[17];
    const float* db3   = (const float*)d_in[18];

    int n = in_sizes[0] / 4;
    int E = in_sizes[1] / 2;

    float* out    = (float*)d_out;
    float* out_mu = out + (size_t)n * 4;
    float* out_lv = out + (size_t)n * 6;

    int nb = (n + 255) / 256;
    int eb = (E + 63) / 64;   // 64 edges per block (4 warps x 16 edges)

    k_zero<<<256, 256>>>(n);
    k_stats<<<256, 256>>>((const float4*)x, n);
    k_pre<<<nb, 256>>>((const float4*)x, gamma, beta, eW1, eb1, n, 1.0f / (float)n);
    k_enc<<<eb, 128>>>(ei, eW2, eb2, mW, vW, E);
    k_mid<<<nb, 256>>>(mb, vb, dW1, db1, eps, out_mu, out_lv, n);
    k_dec<<<eb, 128>>>(ei, dW2, db2, dW3, db3, E);
    k_out<<<nb, 256>>>(out, n);
}